// round 17
// baseline (speedup 1.0000x reference)
#include <cuda_runtime.h>
#include <cuda_fp16.h>
#include <cstdint>

#define B 1024
#define T 128
#define INP 5
#define H 100
#define G4 400
#define MTOT (B*T)
#define KPAD 256          // k-stride of fp16 A/B arrays; 128B-aligned k-slices

// ---------------- scratch (device globals; no runtime allocation) ----------
__device__ float g_h0s[B * 2 * H];            // [b][200] h0 at t=T-1
// xg1 fp16 2-SECTION TILE layout:
//   row = (t*64+bg)*50 + tile   (128 halfs per row)
//   halfs [0:64)  = batches 0-7  of bg: idx g*8 + t4*2 + e  (gates c0,c1)
//   halfs [64:128)= batches 8-15 of bg: same indexing        (gates c2,c3)
__device__ __half g_xg1[(size_t)MTOT * G4];
__device__ float g_h1f[B * H];
__device__ __half g_Ah[(size_t)MTOT * KPAD];  // h0 fp16, [t*B+b][k]; cols 200..255 = 0
__device__ __half g_Bh[400 * KPAD];           // W_ih_l1f fp16, rows gate-interleaved

typedef unsigned long long u64;

__device__ __forceinline__ u64 pk2(float a, float b) {
    u64 r; asm("mov.b64 %0, {%1,%2};" : "=l"(r) : "f"(a), "f"(b)); return r;
}
__device__ __forceinline__ void upk2(u64 v, float& a, float& b) {
    asm("mov.b64 {%0,%1}, %2;" : "=f"(a), "=f"(b) : "l"(v));
}
__device__ __forceinline__ u64 ffma2(u64 a, u64 b, u64 c) {
    asm("fma.rn.f32x2 %0, %1, %2, %0;" : "+l"(c) : "l"(a), "l"(b)); return c;
}
// ---- activations via tanh.approx (1 MUFU each; sigma = 0.5*tanh(x/2)+0.5) --
__device__ __forceinline__ float ftanh_(float x) {
    float t; asm("tanh.approx.f32 %0, %1;" : "=f"(t) : "f"(x)); return t;
}
__device__ __forceinline__ float fsig(float x) {
    float t; asm("tanh.approx.f32 %0, %1;" : "=f"(t) : "f"(x * 0.5f));
    return fmaf(0.5f, t, 0.5f);
}
__device__ __forceinline__ uint32_t smem_u32(const void* p) {
    uint32_t a;
    asm("{ .reg .u64 t; cvta.to.shared.u64 t, %1; cvt.u32.u64 %0, t; }" : "=r"(a) : "l"(p));
    return a;
}

#define MMA_F16(ac, a0,a1,a2,a3, b0,b1) \
    asm volatile("mma.sync.aligned.m16n8k16.row.col.f32.f16.f16.f32 " \
        "{%0,%1,%2,%3}, {%4,%5,%6,%7}, {%8,%9}, {%0,%1,%2,%3};" \
        : "+f"((ac)[0]), "+f"((ac)[1]), "+f"((ac)[2]), "+f"((ac)[3]) \
        : "r"(a0), "r"(a1), "r"(a2), "r"(a3), "r"(b0), "r"(b1))

#define CP_ASYNC16(dst, src) \
    asm volatile("cp.async.ca.shared.global [%0], [%1], 16;" :: "r"(dst), "l"(src))
#define CP_COMMIT() asm volatile("cp.async.commit_group;" ::: "memory")
#define CP_WAIT0()  asm volatile("cp.async.wait_group 0;" ::: "memory")

// ============================================================================
// TENSOR-CORE RECURRENCE, fp16 single-product, W fragments hoisted (56 regs).
// mode 0: layer0 — 16 batches/CTA, grid 128 (dir=bid>>6); coalesced h->global.
// mode 1: layer1 fwd — 8 batches/CTA, grid 128; A rows 8-15 stay zero, odd
//         lanes skip activations (halved MUFU); xg read as __half2/slot.
// ONE barrier/step. SMEM: W[400][120]fp16 | A bufs x2
// ============================================================================
#define KSB     240
#define OFF_A   96000
#define ABUF    3840
#define RC_SMEM (96000 + 2*3840)
#define NTHR    512

__global__ void __launch_bounds__(NTHR, 1) lstm_rec_mma(
    const __half* __restrict__ xg,
    const float* __restrict__ x,
    const float* __restrict__ whf, const float* __restrict__ whb,
    const float* __restrict__ wihf, const float* __restrict__ wihb,
    const float* __restrict__ bihf, const float* __restrict__ bhhf,
    const float* __restrict__ bihb, const float* __restrict__ bhhb,
    int mode)
{
    extern __shared__ char smc[];
    const uint32_t sb = smem_u32(smc);
    const int tid = threadIdx.x, wid = tid >> 5, lane = tid & 31;
    const int g = lane >> 2, t4 = lane & 3;
    const int dir = (mode == 0) ? (int)(blockIdx.x >> 6) : 0;
    const int b0  = (mode == 0) ? (int)(blockIdx.x & 63) * 16 : (int)blockIdx.x * 8;
    const int bg  = b0 >> 4;
    const int sec = (mode == 1) ? ((b0 >> 3) & 1) : 0;
    const float* wp  = dir ? whb  : whf;
    const float* wip = dir ? wihb : wihf;
    const float* bi_ = dir ? bihb : bihf;
    const float* bh_ = dir ? bhhb : bhhf;

    for (int i = tid; i < (RC_SMEM >> 4); i += NTHR)
        ((uint4*)smc)[i] = make_uint4(0, 0, 0, 0);
    __syncthreads();
    // W fill: row n' = j*4+gate <- orig row gate*100+j ; k 0..99 = Whh
    for (int i = tid; i < 400 * 100; i += NTHR) {
        int r = i / 100, k = i - r * 100;
        int np = (r % 100) * 4 + r / 100;
        *(__half*)(smc + np * KSB + k * 2) = __float2half(wp[i]);
    }
    if (mode == 0) {
        for (int i = tid; i < 400 * INP; i += NTHR) {
            int r = i / INP, d = i - r * INP;
            int np = (r % 100) * 4 + r / 100;
            *(__half*)(smc + np * KSB + (100 + d) * 2) = __float2half(wip[i]);
        }
        if (tid < 16 * INP) {
            int bb = tid / INP, d = tid - (tid / INP) * INP;
            int tg0 = dir ? (T - 1) : 0;
            float xv = x[((size_t)(b0 + bb) * T + tg0) * INP + d];
            *(__half*)(smc + OFF_A + bb * KSB + (100 + d) * 2) = __float2half(xv);
        }
    }

    int  tl[4]; bool tv[4];
    float br[4][2];
    #pragma unroll
    for (int i = 0; i < 4; i++) {
        int t = wid + 16 * i;
        tv[i] = (t < 50); tl[i] = tv[i] ? t : 0;
        br[i][0] = br[i][1] = 0.f;
        if (mode == 0 && tv[i]) {
            int np = t * 8 + 2 * t4;
            int r0 = (np & 3) * 100 + (np >> 2);
            int r1 = ((np + 1) & 3) * 100 + ((np + 1) >> 2);
            br[i][0] = bi_[r0] + bh_[r0];
            br[i][1] = bi_[r1] + bh_[r1];
        }
    }
    float cst[4];
    #pragma unroll
    for (int i = 0; i < 4; i++) cst[i] = 0.f;

    __syncthreads();   // W smem complete before fragment preload

    // ---- HOIST: load all W fragments into registers ONCE ----
    uint32_t wreg[7][4][2];
    #pragma unroll
    for (int kc = 0; kc < 7; kc++) {
        #pragma unroll
        for (int p = 0; p < 2; p++) {
            int m = lane >> 3;
            int tt = tl[2 * p + (m >> 1)];
            uint32_t wa = sb + (8 * tt + (lane & 7)) * KSB + (m & 1) * 16 + kc * 32;
            asm volatile("ldmatrix.sync.aligned.m8n8.x4.shared.b16 {%0,%1,%2,%3}, [%4];"
                : "=r"(wreg[kc][2*p][0]), "=r"(wreg[kc][2*p][1]),
                  "=r"(wreg[kc][2*p+1][0]), "=r"(wreg[kc][2*p+1][1])
                : "r"(wa));
        }
    }

    // mode1: one __half2 per slot (batches of this CTA's section only)
    float2 xp[4];
    if (mode == 1) {
        #pragma unroll
        for (int i = 0; i < 4; i++) {
            xp[i] = make_float2(0.f, 0.f);
            if (tv[i])
                xp[i] = __half22float2(*(const __half2*)(xg +
                        ((size_t)bg * 50 + tl[i]) * 128 + sec * 64 + g * 8 + t4 * 2));
        }
    }

    for (int ts = 0; ts < T; ts++) {
        const int cur = ts & 1, nxt = cur ^ 1;
        const int tg = dir ? (T - 1 - ts) : ts;

        float acc[4][4];
        if (mode == 0) {
            #pragma unroll
            for (int i = 0; i < 4; i++) {
                acc[i][0] = br[i][0]; acc[i][1] = br[i][1];
                acc[i][2] = br[i][0]; acc[i][3] = br[i][1];
            }
        } else {
            #pragma unroll
            for (int i = 0; i < 4; i++) {
                acc[i][0] = xp[i].x; acc[i][1] = xp[i].y;   // c0, c1 (batch g)
                acc[i][2] = 0.f;     acc[i][3] = 0.f;       // rows 8-15 unused
            }
            if (ts + 1 < T) {
                #pragma unroll
                for (int i = 0; i < 4; i++)
                    if (tv[i])
                        xp[i] = __half22float2(*(const __half2*)(xg +
                                (((size_t)(ts + 1) * 64 + bg) * 50 + tl[i]) * 128
                                + sec * 64 + g * 8 + t4 * 2));
            }
        }
        float xv = 0.f;
        if (mode == 0 && tid < 16 * INP && ts + 1 < T) {
            int bb = tid / INP, d = tid - (tid / INP) * INP;
            int tgn = dir ? (tg - 1) : (tg + 1);
            xv = x[((size_t)(b0 + bb) * T + tgn) * INP + d];
        }

        // ---- MMA: 7 k-chunks x 4 slots; W from registers, A via ldmatrix ----
        const uint32_t aBase = sb + OFF_A + cur * ABUF;
        #pragma unroll
        for (int kc = 0; kc < 7; kc++) {
            uint32_t ah[4];
            uint32_t aa = aBase + (lane & 15) * KSB + (lane >> 4) * 16 + kc * 32;
            asm volatile("ldmatrix.sync.aligned.m8n8.x4.shared.b16 {%0,%1,%2,%3}, [%4];"
                : "=r"(ah[0]), "=r"(ah[1]), "=r"(ah[2]), "=r"(ah[3]) : "r"(aa));
            #pragma unroll
            for (int i = 0; i < 4; i++)
                MMA_F16(acc[i], ah[0], ah[1], ah[2], ah[3],
                        wreg[kc][i][0], wreg[kc][i][1]);
        }

        // ---- gate exchange + in-register activations ----
        #pragma unroll
        for (int i = 0; i < 4; i++) {
            if (tv[i]) {
                float s0 = __shfl_xor_sync(0xffffffffu, acc[i][0], 1);
                float s1 = __shfl_xor_sync(0xffffffffu, acc[i][1], 1);
                float s2 = __shfl_xor_sync(0xffffffffu, acc[i][2], 1);
                float s3 = __shfl_xor_sync(0xffffffffu, acc[i][3], 1);
                bool odd = (t4 & 1);
                if (mode == 0 || !odd) {
                    float gi = odd ? s2 : acc[i][0];
                    float gf = odd ? s3 : acc[i][1];
                    float gg = odd ? acc[i][2] : s0;
                    float go = odd ? acc[i][3] : s1;
                    float cv = fsig(gf) * cst[i] + fsig(gi) * ftanh_(gg);
                    cst[i] = cv;
                    float h = fsig(go) * ftanh_(cv);
                    int bu = g + (odd ? 8 : 0);
                    int ju = 2 * tl[i] + (t4 >> 1);
                    *(__half*)(smc + OFF_A + nxt * ABUF + bu * KSB + ju * 2) = __float2half(h);
                    if (mode == 0) {
                        if (tg == T - 1)
                            g_h0s[(size_t)(b0 + bu) * 200 + dir * 100 + ju] = h;
                    } else if (ts == T - 1) {
                        g_h1f[(size_t)(b0 + bu) * 100 + ju] = h;
                    }
                }
            }
        }
        if (mode == 0 && tid < 16 * INP && ts + 1 < T) {
            int bb = tid / INP, d = tid - (tid / INP) * INP;
            *(__half*)(smc + OFF_A + nxt * ABUF + bb * KSB + (100 + d) * 2) = __float2half(xv);
        }
        __syncthreads();

        // ---- (mode0) coalesced copy of this step's h to global ----
        if (mode == 0) {
            const char* st = smc + OFF_A + nxt * ABUF;
            if (tid < 400) {
                int row = tid / 25, c8 = tid - row * 25;
                uint2 v = *(const uint2*)(st + row * KSB + c8 * 8);
                size_t gr = ((size_t)tg * B + b0 + row) * KPAD + dir * 100 + c8 * 4;
                *(uint2*)(g_Ah + gr) = v;
            }
        }
    }
}

// ============================================================================
// conv_b: W_ih_l1f -> fp16, rows gate-interleaved (n' = j*4+gate).
// ============================================================================
__global__ void conv_b_kernel(const float* __restrict__ wih)
{
    int i = blockIdx.x * 256 + threadIdx.x;
    if (i < 400 * 200) {
        int r = i / 200, k = i - r * 200;
        int np = (r % 100) * 4 + r / 100;
        g_Bh[np * KPAD + k] = __float2half(wih[i]);
    }
}

// ============================================================================
// xg1 GEMM fp16 single product: BM=128, BN=80, BK=64, 4 iters, cp.async
// double-buffered; epilogue writes fp16 2-section tile layout. grid (5, 1024).
// ============================================================================
#define GRS   72
#define GA_B  (128 * GRS * 2)
#define GB_B  (80 * GRS * 2)
#define GOFF_B  (2 * GA_B)
#define GOFF_BI (2 * GA_B + 2 * GB_B)
#define GSMEM   (GOFF_BI + 1600)

__global__ void __launch_bounds__(256, 3) gemm_xg1_mma(
    const float* __restrict__ bih, const float* __restrict__ bhh)
{
    extern __shared__ char gsm[];
    const uint32_t sbase = smem_u32(gsm);
    float* bsm = (float*)(gsm + GOFF_BI);

    const int tid  = threadIdx.x;
    const int wid  = tid >> 5;
    const int lane = tid & 31;
    const int n0   = blockIdx.x * 80;
    const int m0   = blockIdx.y * 128;
    const int wm   = (wid >> 1) * 32;
    const int wn   = (wid & 1) * 40;

    for (int i = tid; i < 400; i += 256) {
        int r = (i & 3) * 100 + (i >> 2);
        bsm[i] = bih[r] + bhh[r];
    }

    float acc[2][5][4];
    #pragma unroll
    for (int mt = 0; mt < 2; mt++)
        #pragma unroll
        for (int nt = 0; nt < 5; nt++)
            #pragma unroll
            for (int e = 0; e < 4; e++) acc[mt][nt][e] = 0.f;

    const int arow = tid >> 1, ahalf = tid & 1;
    const int brow = tid >> 1, bhalf = tid & 1;
    const uint32_t adst0 = sbase + arow * (GRS * 2) + ahalf * 64;
    const uint32_t bdst0 = sbase + GOFF_B + brow * (GRS * 2) + bhalf * 64;

    {
        const char* ap = (const char*)(g_Ah + (size_t)(m0 + arow) * KPAD + ahalf * 32);
        #pragma unroll
        for (int i = 0; i < 4; i++) CP_ASYNC16(adst0 + i * 16, ap + i * 16);
        if (tid < 160) {
            const char* bp = (const char*)(g_Bh + (size_t)(n0 + brow) * KPAD + bhalf * 32);
            #pragma unroll
            for (int i = 0; i < 4; i++) CP_ASYNC16(bdst0 + i * 16, bp + i * 16);
        }
        CP_COMMIT(); CP_WAIT0();
    }
    __syncthreads();

    for (int it = 0; it < 4; it++) {
        const int cur = it & 1, nxt = cur ^ 1;
        if (it < 3) {
            const int kc = it + 1;
            const char* ap = (const char*)(g_Ah + (size_t)(m0 + arow) * KPAD + kc * 64 + ahalf * 32);
            uint32_t ad = adst0 + nxt * GA_B;
            #pragma unroll
            for (int i = 0; i < 4; i++) CP_ASYNC16(ad + i * 16, ap + i * 16);
            if (tid < 160) {
                const char* bp = (const char*)(g_Bh + (size_t)(n0 + brow) * KPAD + kc * 64 + bhalf * 32);
                uint32_t bd = bdst0 + nxt * GB_B;
                #pragma unroll
                for (int i = 0; i < 4; i++) CP_ASYNC16(bd + i * 16, bp + i * 16);
            }
            CP_COMMIT();
        }

        const uint32_t abuf = sbase + cur * GA_B;
        const uint32_t bbuf = sbase + GOFF_B + cur * GB_B;
        #pragma unroll
        for (int kk = 0; kk < 4; kk++) {
            uint32_t af[2][4];
            #pragma unroll
            for (int mt = 0; mt < 2; mt++) {
                uint32_t addr = abuf + (wm + mt * 16 + (lane & 15)) * (GRS * 2)
                              + (lane >> 4) * 16 + kk * 32;
                asm volatile("ldmatrix.sync.aligned.m8n8.x4.shared.b16 {%0,%1,%2,%3}, [%4];"
                    : "=r"(af[mt][0]), "=r"(af[mt][1]), "=r"(af[mt][2]), "=r"(af[mt][3])
                    : "r"(addr));
            }
            uint32_t bf[5][2];
            #pragma unroll
            for (int nt = 0; nt < 5; nt++) {
                uint32_t addr = bbuf + (wn + nt * 8 + (lane & 7)) * (GRS * 2)
                              + ((lane >> 3) & 1) * 16 + kk * 32;
                asm volatile("ldmatrix.sync.aligned.m8n8.x2.shared.b16 {%0,%1}, [%2];"
                    : "=r"(bf[nt][0]), "=r"(bf[nt][1]) : "r"(addr));
            }
            #pragma unroll
            for (int mt = 0; mt < 2; mt++)
                #pragma unroll
                for (int nt = 0; nt < 5; nt++)
                    MMA_F16(acc[mt][nt], af[mt][0], af[mt][1], af[mt][2], af[mt][3],
                            bf[nt][0], bf[nt][1]);
        }

        if (it < 3) CP_WAIT0();
        __syncthreads();
    }

    // epilogue -> fp16 2-section tile layout
    const int gid = lane >> 2, t4 = lane & 3;
    const int tq = m0 >> 10;
    #pragma unroll
    for (int mt = 0; mt < 2; mt++) {
        int bgq = (((m0 & 1023) + wm + mt * 16) >> 4);
        #pragma unroll
        for (int nt = 0; nt < 5; nt++) {
            int ncol = n0 + wn + nt * 8 + t4 * 2;
            int tile = (n0 + wn) / 8 + nt;
            float b0v = bsm[ncol], b1v = bsm[ncol + 1];
            __half* base = g_xg1 + (((size_t)tq * 64 + bgq) * 50 + tile) * 128;
            *(__half2*)(base + gid * 8 + t4 * 2) =
                __floats2half2_rn(acc[mt][nt][0] + b0v, acc[mt][nt][1] + b1v);
            *(__half2*)(base + 64 + gid * 8 + t4 * 2) =
                __floats2half2_rn(acc[mt][nt][2] + b0v, acc[mt][nt][3] + b1v);
        }
    }
}

// ============================================================================
// lstm_final: layer1 backward single step (c0=0) + FC + softmax. grid 128.
// ============================================================================
#define FN_SMEMF (30000 + 200*10 + 800 + 300 + 600 + 4 + 24)

__global__ void __launch_bounds__(256, 1) lstm_final(
    const float* __restrict__ wih1b,
    const float* __restrict__ bih1b, const float* __restrict__ bhh1b,
    const float* __restrict__ fc_w,  const float* __restrict__ fc_b,
    float* __restrict__ out)
{
    extern __shared__ float sm[];
    float* wT   = sm;
    float* h0s  = sm + 30000;
    float* h1bs = sm + 32000;
    float* b3   = sm + 32800;
    float* fcw  = sm + 33100;
    float* fcb  = sm + 33700;
    float* lg   = sm + 33704;

    const int tid = threadIdx.x;
    const int b0 = blockIdx.x * 8;

    for (int i = tid; i < 8 * 200; i += 256) {
        int b = i / 200, k = i - b * 200;
        h0s[k * 10 + b] = g_h0s[(size_t)(b0 + b) * 200 + k];
    }
    for (int i = tid; i < 300; i += 256) {
        int g3 = i / 100, j = i - g3 * 100;
        int row = j + (g3 == 0 ? 0 : (g3 == 1 ? 200 : 300));
        b3[i] = bih1b[row] + bhh1b[row];
    }
    for (int i = tid; i < 600; i += 256) fcw[i] = fc_w[i];
    if (tid < 3) fcb[tid] = fc_b[tid];

    const int  jj  = tid & 127;
    const int  grp = tid >> 7;
    const bool act = (jj < H);

    u64 acc[2][3];
    #pragma unroll
    for (int p = 0; p < 2; p++)
        #pragma unroll
        for (int g = 0; g < 3; g++) acc[p][g] = pk2(0.f, 0.f);

    for (int kt = 0; kt < 2; kt++) {
        __syncthreads();
        for (int i = tid; i < 30000; i += 256) {
            int k = i % 100, j100 = i / 100;
            int grow = j100 + (j100 >= 100 ? 100 : 0);
            wT[k * 300 + j100] = wih1b[(size_t)grow * 200 + kt * 100 + k];
        }
        __syncthreads();
        if (act) {
            #pragma unroll 2
            for (int k = 0; k < 100; k++) {
                const float* wr = wT + k * 300 + jj;
                u64 w0 = pk2(wr[0], wr[0]);
                u64 w1 = pk2(wr[100], wr[100]);
                u64 w2 = pk2(wr[200], wr[200]);
                const float* hb = h0s + (kt * 100 + k) * 10 + grp * 4;
                #pragma unroll
                for (int p = 0; p < 2; p++) {
                    u64 hv = *(const u64*)(hb + 2 * p);
                    acc[p][0] = ffma2(w0, hv, acc[p][0]);
                    acc[p][1] = ffma2(w1, hv, acc[p][1]);
                    acc[p][2] = ffma2(w2, hv, acc[p][2]);
                }
            }
        }
    }
    if (act) {
        #pragma unroll
        for (int p = 0; p < 2; p++) {
            float i0, i1, g0, g1, o0, o1;
            upk2(acc[p][0], i0, i1);
            upk2(acc[p][1], g0, g1);
            upk2(acc[p][2], o0, o1);
            float bi = b3[jj], bg = b3[100 + jj], bo = b3[200 + jj];
            i0 += bi; i1 += bi; g0 += bg; g1 += bg; o0 += bo; o1 += bo;
            float c0 = fsig(i0) * ftanh_(g0);
            float c1 = fsig(i1) * ftanh_(g1);
            int bl = grp * 4 + 2 * p;
            h1bs[bl * 100 + jj]       = fsig(o0) * ftanh_(c0);
            h1bs[(bl + 1) * 100 + jj] = fsig(o1) * ftanh_(c1);
        }
    }
    __syncthreads();
    if (tid < 24) {
        int b = tid / 3, cls = tid - b * 3;
        float a = fcb[cls];
        const float* h1f = g_h1f + (size_t)(b0 + b) * 100;
        #pragma unroll 4
        for (int j = 0; j < 100; j++) {
            a += h1f[j]            * fcw[cls * 200 + j];
            a += h1bs[b * 100 + j] * fcw[cls * 200 + 100 + j];
        }
        lg[tid] = a;
    }
    __syncthreads();
    if (tid < 8) {
        int b = tid;
        float l0 = lg[b * 3], l1 = lg[b * 3 + 1], l2 = lg[b * 3 + 2];
        float m = fmaxf(l0, fmaxf(l1, l2));
        float e0 = __expf(l0 - m), e1 = __expf(l1 - m), e2 = __expf(l2 - m);
        float s = 1.0f / (e0 + e1 + e2);
        out[(b0 + b) * 3 + 0] = e0 * s;
        out[(b0 + b) * 3 + 1] = e1 * s;
        out[(b0 + b) * 3 + 2] = e2 * s;
    }
}

// ============================================================================
extern "C" void kernel_launch(void* const* d_in, const int* in_sizes, int n_in,
                              void* d_out, int out_size)
{
    (void)in_sizes; (void)n_in; (void)out_size;
    const float* x     = (const float*)d_in[0];
    const float* wih0f = (const float*)d_in[1];
    const float* whh0f = (const float*)d_in[2];
    const float* bih0f = (const float*)d_in[3];
    const float* bhh0f = (const float*)d_in[4];
    const float* wih0b = (const float*)d_in[5];
    const float* whh0b = (const float*)d_in[6];
    const float* bih0b = (const float*)d_in[7];
    const float* bhh0b = (const float*)d_in[8];
    const float* wih1f = (const float*)d_in[9];
    const float* whh1f = (const float*)d_in[10];
    const float* bih1f = (const float*)d_in[11];
    const float* bhh1f = (const float*)d_in[12];
    const float* wih1b = (const float*)d_in[13];
    const float* bih1b = (const float*)d_in[15];
    const float* bhh1b = (const float*)d_in[16];
    const float* fcw   = (const float*)d_in[17];
    const float* fcb   = (const float*)d_in[18];
    float* out = (float*)d_out;

    __half* xg1p; cudaGetSymbolAddress((void**)&xg1p, g_xg1);

    cudaFuncSetAttribute(lstm_rec_mma,  cudaFuncAttributeMaxDynamicSharedMemorySize, RC_SMEM);
    cudaFuncSetAttribute(gemm_xg1_mma,  cudaFuncAttributeMaxDynamicSharedMemorySize, GSMEM);
    cudaFuncSetAttribute(lstm_final,    cudaFuncAttributeMaxDynamicSharedMemorySize, FN_SMEMF * 4);

    conv_b_kernel<<<(400 * 200 + 255) / 256, 256>>>(wih1f);
    lstm_rec_mma<<<128, NTHR, RC_SMEM>>>(nullptr, x, whh0f, whh0b, wih0f, wih0b,
                                         bih0f, bhh0f, bih0b, bhh0b, 0);
    gemm_xg1_mma<<<dim3(5, 1024), 256, GSMEM>>>(bih1f, bhh1f);
    lstm_rec_mma<<<128, NTHR, RC_SMEM>>>(xg1p, nullptr, whh1f, whh1f, wih1f, wih1f,
                                         bih1f, bhh1f, bih1f, bhh1f, 1);
    lstm_final<<<128, 256, FN_SMEMF * 4>>>(wih1b, bih1b, bhh1b, fcw, fcb, out);
}